// round 16
// baseline (speedup 1.0000x reference)
#include <cuda_runtime.h>
#include <cuda_bf16.h>

// out[b,n,m,f] = e0 + e1 * sigmoid((z - e2) * e3),  e = eta_fault[Mask[b,f]]
// sigmoid(x) = 0.5 + 0.5*tanh(0.5*x)  -> single MUFU.TANH per element.
// Folded per-(b,f):  s=0.5*e1 ; a=e0+s ; m=0.5*e3 ; d=e2*m
//   out = fma(s, tanh(fma(z, m, -d)), a)
//
// Geometry gradient (dur_us):
//   1024:86.8 | 2048:86.1 | 4096:84.7 | 8192:84.0 | 16384:82.0 (best)
// This probe: 32768 blocks x 256 threads, 8 contiguous rows/block, ITERS=2.
// Everything else byte-identical to R14.

#define B_DIM 8
#define N_DIM 64
#define M_DIM 512
#define F_DIM 256
#define N_ETA 15

constexpr int NBF           = B_DIM * F_DIM;             // 2048 (b,f) pairs
constexpr int ROWS_PER_B    = N_DIM * M_DIM;             // 32768 rows of 256 floats
constexpr int F4            = F_DIM / 4;                 // 64 float4 per row
constexpr int THREADS       = 256;
constexpr int ROWS_PER_ITER = THREADS / F4;              // 4
constexpr int BLOCKS_PER_B  = 4096;
constexpr int ROWS_PER_BLK  = ROWS_PER_B / BLOCKS_PER_B; // 8 (contiguous per block)
constexpr int ITERS         = ROWS_PER_BLK / ROWS_PER_ITER; // 2

__device__ __forceinline__ float tanh_ap(float x) {
    float r;
    asm("tanh.approx.f32 %0, %1;" : "=f"(r) : "f"(x));
    return r;
}

__global__ __launch_bounds__(THREADS) void sigmoid_rt_fused(
    const float4* __restrict__ z,
    const void*   __restrict__ mask_raw,
    const float4* __restrict__ eta4,     // eta_fault viewed as [15] float4 rows
    float4*       __restrict__ out)
{
    const int b    = blockIdx.x / BLOCKS_PER_B;
    const int blk  = blockIdx.x % BLOCKS_PER_B;
    const int fi   = threadIdx.x & (F4 - 1);   // float4 column (fixed per thread)
    const int rsub = threadIdx.x >> 6;         // row within the 4-row group

    // ---- Mask dtype detection (int64 vs int32), warp-uniform ----
    // int32 view of the first 4KB is safe under both dtypes.
    // int64 (LE): odd words are high halves of values in [0,15) -> all zero.
    // int32: odd words random in [0,15); P(32 zeros) = 15^-32 ~ 0.
    const int* m32 = (const int*)mask_raw;
    const long long* m64 = (const long long*)mask_raw;
    unsigned nz = __ballot_sync(0xffffffffu, m32[2 * threadIdx.x + 1] != 0);
    const bool is64 = (nz == 0u);

    // ---- Prologue: one folded quad per thread through smem, then 4 to regs ----
    __shared__ float4 s_coef[F_DIM];
    {
        const int k = b * F_DIM + threadIdx.x;     // (b, f=threadIdx.x)
        int idx = is64 ? (int)m64[k] : m32[k];
        idx = max(0, min(N_ETA - 1, idx));         // crash-proof under any dtype
        float4 e = eta4[idx];                      // one LDG.128: (e0,e1,e2,e3)
        float s = 0.5f * e.y;
        float m = 0.5f * e.w;
        s_coef[threadIdx.x] = make_float4(s, e.x + s, m, e.z * m);
    }
    __syncthreads();

    float4 c[4];
#pragma unroll
    for (int j = 0; j < 4; ++j)
        c[j] = s_coef[4 * fi + j];

    // ---- Main stream: LDG.128 -> 2 FMA + TANH per lane -> STG.128 ----
    const long base_row = (long)b * ROWS_PER_B + (long)blk * ROWS_PER_BLK + rsub;
    const float4* zp = z   + base_row * F4 + fi;
    float4*       op = out + base_row * F4 + fi;
    const long stride = (long)ROWS_PER_ITER * F4;   // 256 float4 per step

#pragma unroll
    for (int it = 0; it < ITERS; ++it) {
        float4 v = zp[it * stride];
        float4 r;
        r.x = fmaf(c[0].x, tanh_ap(fmaf(v.x, c[0].z, -c[0].w)), c[0].y);
        r.y = fmaf(c[1].x, tanh_ap(fmaf(v.y, c[1].z, -c[1].w)), c[1].y);
        r.z = fmaf(c[2].x, tanh_ap(fmaf(v.z, c[2].z, -c[2].w)), c[2].y);
        r.w = fmaf(c[3].x, tanh_ap(fmaf(v.w, c[3].z, -c[3].w)), c[3].y);
        op[it * stride] = r;
    }
}

extern "C" void kernel_launch(void* const* d_in, const int* in_sizes, int n_in,
                              void* d_out, int out_size)
{
    // Bind inputs by element count — robust to metadata ordering.
    //   z = 67,108,864 ; Mask = 2,048 ; eta_fault = 60
    const float4* z    = nullptr;
    const void*   mask = nullptr;
    const float4* eta4 = nullptr;
    for (int i = 0; i < n_in; ++i) {
        if (in_sizes[i] > 1000000)   z    = (const float4*)d_in[i];
        else if (in_sizes[i] == NBF) mask = d_in[i];
        else                         eta4 = (const float4*)d_in[i];
    }

    sigmoid_rt_fused<<<B_DIM * BLOCKS_PER_B, THREADS>>>(z, mask, eta4, (float4*)d_out);
}

// round 17
// speedup vs baseline: 1.8548x; 1.8548x over previous
#include <cuda_runtime.h>
#include <cuda_bf16.h>

// out[b,n,m,f] = e0 + e1 * sigmoid((z - e2) * e3),  e = eta_fault[Mask[b,f]]
// sigmoid(x) = 0.5 + 0.5*tanh(0.5*x)  -> single MUFU.TANH per element.
// Folded per-(b,f):  s=0.5*e1 ; a=e0+s ; m=0.5*e3 ; d=e2*m
//   out = fma(s, tanh(fma(z, m, -d)), a)
//
// FINAL (converged) configuration — measured optimum of the full sweep:
//   blocks:   1024:86.8 | 2048:86.1 | 4096:84.7 | 8192:84.0 | *16384:82.0* | 32768:152 (cliff)
//   unroll 8 (R9), .cs hints (R5), single-wave stride (R8), 512-thr blocks (R11),
//   per-iter smem operands (R7/R16): all regressions.
// 16384 blocks x 256 threads, 16 contiguous rows/block, ITERS=4, register-resident
// coefficients, plain LDG/STG. Sustains ~6.3 TB/s = chip's R/W-mix ceiling.

#define B_DIM 8
#define N_DIM 64
#define M_DIM 512
#define F_DIM 256
#define N_ETA 15

constexpr int NBF           = B_DIM * F_DIM;             // 2048 (b,f) pairs
constexpr int ROWS_PER_B    = N_DIM * M_DIM;             // 32768 rows of 256 floats
constexpr int F4            = F_DIM / 4;                 // 64 float4 per row
constexpr int THREADS       = 256;
constexpr int ROWS_PER_ITER = THREADS / F4;              // 4
constexpr int BLOCKS_PER_B  = 2048;
constexpr int ROWS_PER_BLK  = ROWS_PER_B / BLOCKS_PER_B; // 16 (contiguous per block)
constexpr int ITERS         = ROWS_PER_BLK / ROWS_PER_ITER; // 4

__device__ __forceinline__ float tanh_ap(float x) {
    float r;
    asm("tanh.approx.f32 %0, %1;" : "=f"(r) : "f"(x));
    return r;
}

__global__ __launch_bounds__(THREADS) void sigmoid_rt_fused(
    const float4* __restrict__ z,
    const void*   __restrict__ mask_raw,
    const float4* __restrict__ eta4,     // eta_fault viewed as [15] float4 rows
    float4*       __restrict__ out)
{
    const int b    = blockIdx.x / BLOCKS_PER_B;
    const int blk  = blockIdx.x % BLOCKS_PER_B;
    const int fi   = threadIdx.x & (F4 - 1);   // float4 column (fixed per thread)
    const int rsub = threadIdx.x >> 6;         // row within the 4-row group

    // ---- Mask dtype detection (int64 vs int32), warp-uniform ----
    // int32 view of the first 4KB is safe under both dtypes.
    // int64 (LE): odd words are high halves of values in [0,15) -> all zero.
    // int32: odd words random in [0,15); P(32 zeros) = 15^-32 ~ 0.
    const int* m32 = (const int*)mask_raw;
    const long long* m64 = (const long long*)mask_raw;
    unsigned nz = __ballot_sync(0xffffffffu, m32[2 * threadIdx.x + 1] != 0);
    const bool is64 = (nz == 0u);

    // ---- Prologue: one folded quad per thread through smem, then 4 to regs ----
    __shared__ float4 s_coef[F_DIM];
    {
        const int k = b * F_DIM + threadIdx.x;     // (b, f=threadIdx.x)
        int idx = is64 ? (int)m64[k] : m32[k];
        idx = max(0, min(N_ETA - 1, idx));         // crash-proof under any dtype
        float4 e = eta4[idx];                      // one LDG.128: (e0,e1,e2,e3)
        float s = 0.5f * e.y;
        float m = 0.5f * e.w;
        s_coef[threadIdx.x] = make_float4(s, e.x + s, m, e.z * m);
    }
    __syncthreads();

    float4 c[4];
#pragma unroll
    for (int j = 0; j < 4; ++j)
        c[j] = s_coef[4 * fi + j];

    // ---- Main stream: LDG.128 -> 2 FMA + TANH per lane -> STG.128 ----
    const long base_row = (long)b * ROWS_PER_B + (long)blk * ROWS_PER_BLK + rsub;
    const float4* zp = z   + base_row * F4 + fi;
    float4*       op = out + base_row * F4 + fi;
    const long stride = (long)ROWS_PER_ITER * F4;   // 256 float4 per step

#pragma unroll
    for (int it = 0; it < ITERS; ++it) {
        float4 v = zp[it * stride];
        float4 r;
        r.x = fmaf(c[0].x, tanh_ap(fmaf(v.x, c[0].z, -c[0].w)), c[0].y);
        r.y = fmaf(c[1].x, tanh_ap(fmaf(v.y, c[1].z, -c[1].w)), c[1].y);
        r.z = fmaf(c[2].x, tanh_ap(fmaf(v.z, c[2].z, -c[2].w)), c[2].y);
        r.w = fmaf(c[3].x, tanh_ap(fmaf(v.w, c[3].z, -c[3].w)), c[3].y);
        op[it * stride] = r;
    }
}

extern "C" void kernel_launch(void* const* d_in, const int* in_sizes, int n_in,
                              void* d_out, int out_size)
{
    // Bind inputs by element count — robust to metadata ordering.
    //   z = 67,108,864 ; Mask = 2,048 ; eta_fault = 60
    const float4* z    = nullptr;
    const void*   mask = nullptr;
    const float4* eta4 = nullptr;
    for (int i = 0; i < n_in; ++i) {
        if (in_sizes[i] > 1000000)   z    = (const float4*)d_in[i];
        else if (in_sizes[i] == NBF) mask = d_in[i];
        else                         eta4 = (const float4*)d_in[i];
    }

    sigmoid_rt_fused<<<B_DIM * BLOCKS_PER_B, THREADS>>>(z, mask, eta4, (float4*)d_out);
}